// round 2
// baseline (speedup 1.0000x reference)
#include <cuda_runtime.h>
#include <cuda_fp16.h>
#include <cstdint>

#define T_TOK 4096
#define DDIM  1024
#define NEXP  8
#define FDIM  2816
#define TWOF  5632
#define NASS  8192          // T*K assignments
#define CAP   9216          // padded grouped-row capacity
#define MAXMT 80            // max 128-row tiles
#define NT1   44            // FDIM/64 column tiles (gate+up interleaved -> 128 B-rows)
#define NT2   8             // DDIM/128 column tiles

// ---------------- scratch: device globals (no allocation allowed) ----------------
__device__ __half g_xh [(size_t)T_TOK * DDIM];
__device__ __half g_wgu[(size_t)NEXP * TWOF * DDIM];
__device__ __half g_wdn[(size_t)NEXP * DDIM * FDIM];
__device__ __half g_act[(size_t)CAP * FDIM];
__device__ float  g_og [(size_t)CAP * DDIM];
__device__ int    g_tok[CAP];
__device__ float  g_wt [CAP];
__device__ int    g_pos[NASS];
__device__ int    g_mt_e[MAXMT];
__device__ int    g_mt_base[MAXMT];
__device__ int    g_nm;

// ---------------- PTX helpers ----------------
__device__ __forceinline__ uint32_t smem_u32(const void* p) {
    uint32_t a;
    asm("{ .reg .u64 t; cvta.to.shared.u64 t, %1; cvt.u32.u64 %0, t; }" : "=r"(a) : "l"(p));
    return a;
}
__device__ __forceinline__ void cp16(uint32_t dst, const void* src) {
    asm volatile("cp.async.cg.shared.global [%0], [%1], 16;" :: "r"(dst), "l"(src));
}
#define CP_COMMIT asm volatile("cp.async.commit_group;")
#define CP_WAIT1  asm volatile("cp.async.wait_group 1;")

#define LDSM4(r0, r1, r2, r3, addr) \
    asm volatile("ldmatrix.sync.aligned.m8n8.x4.shared.b16 {%0,%1,%2,%3}, [%4];" \
        : "=r"(r0), "=r"(r1), "=r"(r2), "=r"(r3) : "r"(addr))

#define MMA16816(c, a, b) \
    asm volatile("mma.sync.aligned.m16n8k16.row.col.f32.f16.f16.f32 " \
        "{%0,%1,%2,%3},{%4,%5,%6,%7},{%8,%9},{%0,%1,%2,%3};" \
        : "+f"((c)[0]), "+f"((c)[1]), "+f"((c)[2]), "+f"((c)[3]) \
        : "r"((a)[0]), "r"((a)[1]), "r"((a)[2]), "r"((a)[3]), \
          "r"((b)[0]), "r"((b)[1]))

// ---------------- routing prep (1 block) ----------------
__global__ void prep_kernel(const int* __restrict__ ids, const float* __restrict__ wts) {
    __shared__ int cnt[NEXP], off[NEXP], cur[NEXP];
    int tid = threadIdx.x;
    if (tid < NEXP) { cnt[tid] = 0; cur[tid] = 0; }
    __syncthreads();
    for (int i = tid; i < NASS; i += 256) atomicAdd(&cnt[ids[i]], 1);
    __syncthreads();
    if (tid == 0) {
        int o = 0, nm = 0;
        for (int e = 0; e < NEXP; e++) {
            off[e] = o;
            int pad = (cnt[e] + 127) & ~127;
            for (int b = 0; b < pad; b += 128) { g_mt_e[nm] = e; g_mt_base[nm] = o + b; nm++; }
            o += pad;
        }
        g_nm = nm;
    }
    __syncthreads();
    for (int s = tid; s < CAP; s += 256) { g_tok[s] = 0; g_wt[s] = 0.f; }
    __syncthreads();
    for (int i = tid; i < NASS; i += 256) {
        int e = ids[i];
        int r = atomicAdd(&cur[e], 1);   // slot order nondeterministic, values slot-independent
        int slot = off[e] + r;
        g_pos[i] = slot;
        g_tok[slot] = i >> 1;
        g_wt[slot] = wts[i];
    }
}

// ---------------- fp32 -> fp16 convert ----------------
__global__ void cvt_kernel(const float* __restrict__ s, int which, int n4) {
    int i = blockIdx.x * 256 + threadIdx.x;
    if (i >= n4) return;
    __half* d = (which == 0) ? g_xh : (which == 1) ? g_wgu : g_wdn;
    float4 v = reinterpret_cast<const float4*>(s)[i];
    __half2* o = reinterpret_cast<__half2*>(d);
    o[2 * (size_t)i]     = __floats2half2_rn(v.x, v.y);
    o[2 * (size_t)i + 1] = __floats2half2_rn(v.z, v.w);
}

// ---------------- GEMM1: h = x @ gate_up^T, fused SiLU(gate)*up -> g_act (fp16) ----------------
// CTA tile: 128 rows x 128 B-rows (64 gate + 64 up interleaved: even nn = gate, odd nn = up)
__global__ void __launch_bounds__(256, 2) gemm1_kernel() {
    int mt = blockIdx.y;
    if (mt >= g_nm) return;
    int e = g_mt_e[mt], base = g_mt_base[mt], ct = blockIdx.x;

    __shared__ __align__(16) __half As[2 * 128 * 40];
    __shared__ __align__(16) __half Bs[2 * 128 * 40];

    int tid = threadIdx.x, lane = tid & 31, wid = tid >> 5;
    int wm = wid & 3, wn = wid >> 2, g = lane >> 2, tg = lane & 3;

    // global->shared load mapping: 2 A rows + 2 B rows per thread, 16B chunks
    int rA = tid >> 2, chunk = tid & 3;
    const __half* a0 = g_xh + (size_t)g_tok[base + rA] * DDIM + chunk * 8;
    const __half* a1 = g_xh + (size_t)g_tok[base + rA + 64] * DDIM + chunk * 8;
    int nn0 = rA, nn1 = rA + 64;
    int wr0 = ((nn0 & 1) ? FDIM : 0) + ct * 64 + (nn0 >> 1);
    int wr1 = ((nn1 & 1) ? FDIM : 0) + ct * 64 + (nn1 >> 1);
    const __half* b0p = g_wgu + ((size_t)e * TWOF + wr0) * DDIM + chunk * 8;
    const __half* b1p = g_wgu + ((size_t)e * TWOF + wr1) * DDIM + chunk * 8;

    uint32_t sA = smem_u32(As), sB = smem_u32(Bs);
    uint32_t dA0 = sA + (rA * 40 + chunk * 8) * 2;
    uint32_t dA1 = sA + ((rA + 64) * 40 + chunk * 8) * 2;
    uint32_t dB0 = sB + (rA * 40 + chunk * 8) * 2;
    uint32_t dB1 = sB + ((rA + 64) * 40 + chunk * 8) * 2;
    const uint32_t BUFB = 128 * 40 * 2;

    float acc[2][8][4];
    #pragma unroll
    for (int i = 0; i < 2; i++)
        #pragma unroll
        for (int j = 0; j < 8; j++)
            acc[i][j][0] = acc[i][j][1] = acc[i][j][2] = acc[i][j][3] = 0.f;

    uint32_t aRowLd = wm * 32 + ((lane >> 3) & 1) * 8 + (lane & 7);
    uint32_t aColLd = ((lane >> 4) & 1) * 8;
    uint32_t bRowLd = wn * 64 + ((lane >> 4) & 1) * 8 + (lane & 7);
    uint32_t bColLd = ((lane >> 3) & 1) * 8;

    cp16(dA0, a0); cp16(dA1, a1); cp16(dB0, b0p); cp16(dB1, b1p);
    CP_COMMIT;

    const int NK = DDIM / 32;
    for (int ks = 0; ks < NK; ks++) {
        int buf = ks & 1;
        if (ks + 1 < NK) {
            int kk = (ks + 1) * 32;
            uint32_t bo = (buf ^ 1) * BUFB;
            cp16(dA0 + bo, a0 + kk); cp16(dA1 + bo, a1 + kk);
            cp16(dB0 + bo, b0p + kk); cp16(dB1 + bo, b1p + kk);
        }
        CP_COMMIT;
        CP_WAIT1;
        __syncthreads();
        uint32_t bo = buf * BUFB;
        #pragma unroll
        for (int kh = 0; kh < 2; kh++) {
            uint32_t af[2][4];
            #pragma unroll
            for (int i = 0; i < 2; i++) {
                uint32_t ad = sA + bo + ((aRowLd + i * 16) * 40 + aColLd + kh * 16) * 2;
                LDSM4(af[i][0], af[i][1], af[i][2], af[i][3], ad);
            }
            uint32_t bf[8][2];
            #pragma unroll
            for (int jp = 0; jp < 4; jp++) {
                uint32_t bd = sB + bo + ((bRowLd + jp * 16) * 40 + bColLd + kh * 16) * 2;
                LDSM4(bf[jp * 2][0], bf[jp * 2][1], bf[jp * 2 + 1][0], bf[jp * 2 + 1][1], bd);
            }
            #pragma unroll
            for (int i = 0; i < 2; i++)
                #pragma unroll
                for (int j = 0; j < 8; j++)
                    MMA16816(acc[i][j], af[i], bf[j]);
        }
        __syncthreads();
    }

    // epilogue: c0=gate(even nn), c1=up(odd nn) -> act = silu(gate)*up
    #pragma unroll
    for (int i = 0; i < 2; i++) {
        int r0 = base + wm * 32 + i * 16 + g;
        int r1 = r0 + 8;
        #pragma unroll
        for (int j = 0; j < 8; j++) {
            int f = ct * 64 + wn * 32 + j * 4 + tg;
            float ga = acc[i][j][0], up = acc[i][j][1];
            g_act[(size_t)r0 * FDIM + f] = __float2half_rn(ga / (1.f + __expf(-ga)) * up);
            ga = acc[i][j][2]; up = acc[i][j][3];
            g_act[(size_t)r1 * FDIM + f] = __float2half_rn(ga / (1.f + __expf(-ga)) * up);
        }
    }
}

// ---------------- GEMM2: og = (act @ down^T) * route_weight -> g_og (fp32) ----------------
__global__ void __launch_bounds__(256, 2) gemm2_kernel() {
    int mt = blockIdx.y;
    if (mt >= g_nm) return;
    int e = g_mt_e[mt], base = g_mt_base[mt], ct = blockIdx.x;

    __shared__ __align__(16) __half As[2 * 128 * 40];
    __shared__ __align__(16) __half Bs[2 * 128 * 40];

    int tid = threadIdx.x, lane = tid & 31, wid = tid >> 5;
    int wm = wid & 3, wn = wid >> 2, g = lane >> 2, tg = lane & 3;

    int rA = tid >> 2, chunk = tid & 3;
    const __half* a0 = g_act + (size_t)(base + rA) * FDIM + chunk * 8;
    const __half* a1 = g_act + (size_t)(base + rA + 64) * FDIM + chunk * 8;
    const __half* b0p = g_wdn + ((size_t)e * DDIM + ct * 128 + rA) * FDIM + chunk * 8;
    const __half* b1p = g_wdn + ((size_t)e * DDIM + ct * 128 + rA + 64) * FDIM + chunk * 8;

    uint32_t sA = smem_u32(As), sB = smem_u32(Bs);
    uint32_t dA0 = sA + (rA * 40 + chunk * 8) * 2;
    uint32_t dA1 = sA + ((rA + 64) * 40 + chunk * 8) * 2;
    uint32_t dB0 = sB + (rA * 40 + chunk * 8) * 2;
    uint32_t dB1 = sB + ((rA + 64) * 40 + chunk * 8) * 2;
    const uint32_t BUFB = 128 * 40 * 2;

    float acc[2][8][4];
    #pragma unroll
    for (int i = 0; i < 2; i++)
        #pragma unroll
        for (int j = 0; j < 8; j++)
            acc[i][j][0] = acc[i][j][1] = acc[i][j][2] = acc[i][j][3] = 0.f;

    uint32_t aRowLd = wm * 32 + ((lane >> 3) & 1) * 8 + (lane & 7);
    uint32_t aColLd = ((lane >> 4) & 1) * 8;
    uint32_t bRowLd = wn * 64 + ((lane >> 4) & 1) * 8 + (lane & 7);
    uint32_t bColLd = ((lane >> 3) & 1) * 8;

    cp16(dA0, a0); cp16(dA1, a1); cp16(dB0, b0p); cp16(dB1, b1p);
    CP_COMMIT;

    const int NK = FDIM / 32;   // 88
    for (int ks = 0; ks < NK; ks++) {
        int buf = ks & 1;
        if (ks + 1 < NK) {
            int kk = (ks + 1) * 32;
            uint32_t bo = (buf ^ 1) * BUFB;
            cp16(dA0 + bo, a0 + kk); cp16(dA1 + bo, a1 + kk);
            cp16(dB0 + bo, b0p + kk); cp16(dB1 + bo, b1p + kk);
        }
        CP_COMMIT;
        CP_WAIT1;
        __syncthreads();
        uint32_t bo = buf * BUFB;
        #pragma unroll
        for (int kh = 0; kh < 2; kh++) {
            uint32_t af[2][4];
            #pragma unroll
            for (int i = 0; i < 2; i++) {
                uint32_t ad = sA + bo + ((aRowLd + i * 16) * 40 + aColLd + kh * 16) * 2;
                LDSM4(af[i][0], af[i][1], af[i][2], af[i][3], ad);
            }
            uint32_t bf[8][2];
            #pragma unroll
            for (int jp = 0; jp < 4; jp++) {
                uint32_t bd = sB + bo + ((bRowLd + jp * 16) * 40 + bColLd + kh * 16) * 2;
                LDSM4(bf[jp * 2][0], bf[jp * 2][1], bf[jp * 2 + 1][0], bf[jp * 2 + 1][1], bd);
            }
            #pragma unroll
            for (int i = 0; i < 2; i++)
                #pragma unroll
                for (int j = 0; j < 8; j++)
                    MMA16816(acc[i][j], af[i], bf[j]);
        }
        __syncthreads();
    }

    #pragma unroll
    for (int i = 0; i < 2; i++) {
        int r0 = base + wm * 32 + i * 16 + g;
        int r1 = r0 + 8;
        float w0 = g_wt[r0], w1 = g_wt[r1];
        #pragma unroll
        for (int j = 0; j < 8; j++) {
            int d = ct * 128 + wn * 64 + j * 8 + 2 * tg;
            float2 v0 = make_float2(acc[i][j][0] * w0, acc[i][j][1] * w0);
            float2 v1 = make_float2(acc[i][j][2] * w1, acc[i][j][3] * w1);
            *reinterpret_cast<float2*>(g_og + (size_t)r0 * DDIM + d) = v0;
            *reinterpret_cast<float2*>(g_og + (size_t)r1 * DDIM + d) = v1;
        }
    }
}

// ---------------- combine: out[t] = og[pos0] + og[pos1] ----------------
__global__ void combine_kernel(float* __restrict__ out) {
    int t = blockIdx.x, c = threadIdx.x;  // 256 threads = 1024 floats / 4
    int p0 = g_pos[2 * t], p1 = g_pos[2 * t + 1];
    const float4* r0 = reinterpret_cast<const float4*>(g_og + (size_t)p0 * DDIM);
    const float4* r1 = reinterpret_cast<const float4*>(g_og + (size_t)p1 * DDIM);
    float4 a = r0[c], b = r1[c];
    float4 w = make_float4(a.x + b.x, a.y + b.y, a.z + b.z, a.w + b.w);
    reinterpret_cast<float4*>(out + (size_t)t * DDIM)[c] = w;
}

// ---------------- launch ----------------
extern "C" void kernel_launch(void* const* d_in, const int* in_sizes, int n_in,
                              void* d_out, int out_size) {
    const float* x   = (const float*)d_in[0];
    const float* gup = (const float*)d_in[1];
    const float* dwn = (const float*)d_in[2];
    const float* tw  = (const float*)d_in[3];
    const int*   ti  = (const int*)d_in[4];
    float* out = (float*)d_out;

    prep_kernel<<<1, 256>>>(ti, tw);

    int n4x = T_TOK * DDIM / 4;                 // 1048576
    int n4g = NEXP * TWOF * DDIM / 4;           // 11534336
    int n4d = NEXP * DDIM * FDIM / 4;           // 5767168
    cvt_kernel<<<(n4x + 255) / 256, 256>>>(x,   0, n4x);
    cvt_kernel<<<(n4g + 255) / 256, 256>>>(gup, 1, n4g);
    cvt_kernel<<<(n4d + 255) / 256, 256>>>(dwn, 2, n4d);

    gemm1_kernel<<<dim3(NT1, MAXMT), 256>>>();
    gemm2_kernel<<<dim3(NT2, MAXMT), 256>>>();

    combine_kernel<<<T_TOK, 256>>>(out);
}

// round 3
// speedup vs baseline: 1.0054x; 1.0054x over previous
#include <cuda_runtime.h>
#include <cuda_fp16.h>
#include <cstdint>

#define T_TOK 4096
#define DDIM  1024
#define NEXP  8
#define FDIM  2816
#define TWOF  5632
#define NASS  8192          // T*K assignments
#define CAP   9216          // padded grouped-row capacity
#define MAXMT 80            // max 128-row tiles
#define NT1   44            // FDIM/64 column tiles (gate+up interleaved -> 128 B-rows)
#define NT2   8             // DDIM/128 column tiles

// ---------------- scratch: device globals (no allocation allowed) ----------------
__device__ __half g_xh [(size_t)T_TOK * DDIM];
__device__ __half g_wgu[(size_t)NEXP * TWOF * DDIM];
__device__ __half g_wdn[(size_t)NEXP * DDIM * FDIM];
__device__ __half g_act[(size_t)CAP * FDIM];
__device__ float  g_og [(size_t)CAP * DDIM];
__device__ int    g_tok[CAP];
__device__ float  g_wt [CAP];
__device__ int    g_pos[NASS];
__device__ int    g_mt_e[MAXMT];
__device__ int    g_mt_base[MAXMT];
__device__ int    g_nm;

// ---------------- PTX helpers ----------------
__device__ __forceinline__ uint32_t smem_u32(const void* p) {
    uint32_t a;
    asm("{ .reg .u64 t; cvta.to.shared.u64 t, %1; cvt.u32.u64 %0, t; }" : "=r"(a) : "l"(p));
    return a;
}
__device__ __forceinline__ void cp16(uint32_t dst, const void* src) {
    asm volatile("cp.async.cg.shared.global [%0], [%1], 16;" :: "r"(dst), "l"(src));
}
#define CP_COMMIT asm volatile("cp.async.commit_group;")
#define CP_WAIT1  asm volatile("cp.async.wait_group 1;")

#define LDSM4(r0, r1, r2, r3, addr) \
    asm volatile("ldmatrix.sync.aligned.m8n8.x4.shared.b16 {%0,%1,%2,%3}, [%4];" \
        : "=r"(r0), "=r"(r1), "=r"(r2), "=r"(r3) : "r"(addr))

#define MMA16816(c, a, b) \
    asm volatile("mma.sync.aligned.m16n8k16.row.col.f32.f16.f16.f32 " \
        "{%0,%1,%2,%3},{%4,%5,%6,%7},{%8,%9},{%0,%1,%2,%3};" \
        : "+f"((c)[0]), "+f"((c)[1]), "+f"((c)[2]), "+f"((c)[3]) \
        : "r"((a)[0]), "r"((a)[1]), "r"((a)[2]), "r"((a)[3]), \
          "r"((b)[0]), "r"((b)[1]))

// ---------------- routing prep (1 block) ----------------
__global__ void prep_kernel(const int* __restrict__ ids, const float* __restrict__ wts) {
    __shared__ int cnt[NEXP], off[NEXP], cur[NEXP];
    int tid = threadIdx.x;
    if (tid < NEXP) { cnt[tid] = 0; cur[tid] = 0; }
    __syncthreads();
    for (int i = tid; i < NASS; i += 256) atomicAdd(&cnt[ids[i]], 1);
    __syncthreads();
    if (tid == 0) {
        int o = 0, nm = 0;
        for (int e = 0; e < NEXP; e++) {
            off[e] = o;
            int pad = (cnt[e] + 127) & ~127;
            for (int b = 0; b < pad; b += 128) { g_mt_e[nm] = e; g_mt_base[nm] = o + b; nm++; }
            o += pad;
        }
        g_nm = nm;
    }
    __syncthreads();
    for (int s = tid; s < CAP; s += 256) { g_tok[s] = 0; g_wt[s] = 0.f; }
    __syncthreads();
    for (int i = tid; i < NASS; i += 256) {
        int e = ids[i];
        int r = atomicAdd(&cur[e], 1);   // slot order nondeterministic, values slot-independent
        int slot = off[e] + r;
        g_pos[i] = slot;
        g_tok[slot] = i >> 1;
        g_wt[slot] = wts[i];
    }
}

// ---------------- fp32 -> fp16 convert ----------------
__global__ void cvt_kernel(const float* __restrict__ s, int which, int n4) {
    int i = blockIdx.x * 256 + threadIdx.x;
    if (i >= n4) return;
    __half* d = (which == 0) ? g_xh : (which == 1) ? g_wgu : g_wdn;
    float4 v = reinterpret_cast<const float4*>(s)[i];
    __half2* o = reinterpret_cast<__half2*>(d);
    o[2 * (size_t)i]     = __floats2half2_rn(v.x, v.y);
    o[2 * (size_t)i + 1] = __floats2half2_rn(v.z, v.w);
}

// ---------------- GEMM1: h = x @ gate_up^T, fused SiLU(gate)*up -> g_act (fp16) ----------------
// CTA tile: 128 rows x 128 B-rows (64 gate + 64 up interleaved: even nn = gate, odd nn = up)
__global__ void __launch_bounds__(256, 2) gemm1_kernel() {
    int mt = blockIdx.y;
    if (mt >= g_nm) return;
    int e = g_mt_e[mt], base = g_mt_base[mt], ct = blockIdx.x;

    __shared__ __align__(16) __half As[2 * 128 * 40];
    __shared__ __align__(16) __half Bs[2 * 128 * 40];

    int tid = threadIdx.x, lane = tid & 31, wid = tid >> 5;
    int wm = wid & 3, wn = wid >> 2, g = lane >> 2, tg = lane & 3;

    // global->shared load mapping: 2 A rows + 2 B rows per thread, 16B chunks
    int rA = tid >> 2, chunk = tid & 3;
    const __half* a0 = g_xh + (size_t)g_tok[base + rA] * DDIM + chunk * 8;
    const __half* a1 = g_xh + (size_t)g_tok[base + rA + 64] * DDIM + chunk * 8;
    int nn0 = rA, nn1 = rA + 64;
    int wr0 = ((nn0 & 1) ? FDIM : 0) + ct * 64 + (nn0 >> 1);
    int wr1 = ((nn1 & 1) ? FDIM : 0) + ct * 64 + (nn1 >> 1);
    const __half* b0p = g_wgu + ((size_t)e * TWOF + wr0) * DDIM + chunk * 8;
    const __half* b1p = g_wgu + ((size_t)e * TWOF + wr1) * DDIM + chunk * 8;

    uint32_t sA = smem_u32(As), sB = smem_u32(Bs);
    uint32_t dA0 = sA + (rA * 40 + chunk * 8) * 2;
    uint32_t dA1 = sA + ((rA + 64) * 40 + chunk * 8) * 2;
    uint32_t dB0 = sB + (rA * 40 + chunk * 8) * 2;
    uint32_t dB1 = sB + ((rA + 64) * 40 + chunk * 8) * 2;
    const uint32_t BUFB = 128 * 40 * 2;

    float acc[2][8][4];
    #pragma unroll
    for (int i = 0; i < 2; i++)
        #pragma unroll
        for (int j = 0; j < 8; j++)
            acc[i][j][0] = acc[i][j][1] = acc[i][j][2] = acc[i][j][3] = 0.f;

    uint32_t aRowLd = wm * 32 + ((lane >> 3) & 1) * 8 + (lane & 7);
    uint32_t aColLd = ((lane >> 4) & 1) * 8;
    uint32_t bRowLd = wn * 64 + ((lane >> 4) & 1) * 8 + (lane & 7);
    uint32_t bColLd = ((lane >> 3) & 1) * 8;

    cp16(dA0, a0); cp16(dA1, a1); cp16(dB0, b0p); cp16(dB1, b1p);
    CP_COMMIT;

    const int NK = DDIM / 32;
    for (int ks = 0; ks < NK; ks++) {
        int buf = ks & 1;
        if (ks + 1 < NK) {
            int kk = (ks + 1) * 32;
            uint32_t bo = (buf ^ 1) * BUFB;
            cp16(dA0 + bo, a0 + kk); cp16(dA1 + bo, a1 + kk);
            cp16(dB0 + bo, b0p + kk); cp16(dB1 + bo, b1p + kk);
        }
        CP_COMMIT;
        CP_WAIT1;
        __syncthreads();
        uint32_t bo = buf * BUFB;
        #pragma unroll
        for (int kh = 0; kh < 2; kh++) {
            uint32_t af[2][4];
            #pragma unroll
            for (int i = 0; i < 2; i++) {
                uint32_t ad = sA + bo + ((aRowLd + i * 16) * 40 + aColLd + kh * 16) * 2;
                LDSM4(af[i][0], af[i][1], af[i][2], af[i][3], ad);
            }
            uint32_t bf[8][2];
            #pragma unroll
            for (int jp = 0; jp < 4; jp++) {
                uint32_t bd = sB + bo + ((bRowLd + jp * 16) * 40 + bColLd + kh * 16) * 2;
                LDSM4(bf[jp * 2][0], bf[jp * 2][1], bf[jp * 2 + 1][0], bf[jp * 2 + 1][1], bd);
            }
            #pragma unroll
            for (int i = 0; i < 2; i++)
                #pragma unroll
                for (int j = 0; j < 8; j++)
                    MMA16816(acc[i][j], af[i], bf[j]);
        }
        __syncthreads();
    }

    // epilogue: c0=gate(even nn), c1=up(odd nn) -> act = silu(gate)*up
    #pragma unroll
    for (int i = 0; i < 2; i++) {
        int r0 = base + wm * 32 + i * 16 + g;
        int r1 = r0 + 8;
        #pragma unroll
        for (int j = 0; j < 8; j++) {
            int f = ct * 64 + wn * 32 + j * 4 + tg;
            float ga = acc[i][j][0], up = acc[i][j][1];
            g_act[(size_t)r0 * FDIM + f] = __float2half_rn(ga / (1.f + __expf(-ga)) * up);
            ga = acc[i][j][2]; up = acc[i][j][3];
            g_act[(size_t)r1 * FDIM + f] = __float2half_rn(ga / (1.f + __expf(-ga)) * up);
        }
    }
}

// ---------------- GEMM2: og = (act @ down^T) * route_weight -> g_og (fp32) ----------------
__global__ void __launch_bounds__(256, 2) gemm2_kernel() {
    int mt = blockIdx.y;
    if (mt >= g_nm) return;
    int e = g_mt_e[mt], base = g_mt_base[mt], ct = blockIdx.x;

    __shared__ __align__(16) __half As[2 * 128 * 40];
    __shared__ __align__(16) __half Bs[2 * 128 * 40];

    int tid = threadIdx.x, lane = tid & 31, wid = tid >> 5;
    int wm = wid & 3, wn = wid >> 2, g = lane >> 2, tg = lane & 3;

    int rA = tid >> 2, chunk = tid & 3;
    const __half* a0 = g_act + (size_t)(base + rA) * FDIM + chunk * 8;
    const __half* a1 = g_act + (size_t)(base + rA + 64) * FDIM + chunk * 8;
    const __half* b0p = g_wdn + ((size_t)e * DDIM + ct * 128 + rA) * FDIM + chunk * 8;
    const __half* b1p = g_wdn + ((size_t)e * DDIM + ct * 128 + rA + 64) * FDIM + chunk * 8;

    uint32_t sA = smem_u32(As), sB = smem_u32(Bs);
    uint32_t dA0 = sA + (rA * 40 + chunk * 8) * 2;
    uint32_t dA1 = sA + ((rA + 64) * 40 + chunk * 8) * 2;
    uint32_t dB0 = sB + (rA * 40 + chunk * 8) * 2;
    uint32_t dB1 = sB + ((rA + 64) * 40 + chunk * 8) * 2;
    const uint32_t BUFB = 128 * 40 * 2;

    float acc[2][8][4];
    #pragma unroll
    for (int i = 0; i < 2; i++)
        #pragma unroll
        for (int j = 0; j < 8; j++)
            acc[i][j][0] = acc[i][j][1] = acc[i][j][2] = acc[i][j][3] = 0.f;

    uint32_t aRowLd = wm * 32 + ((lane >> 3) & 1) * 8 + (lane & 7);
    uint32_t aColLd = ((lane >> 4) & 1) * 8;
    uint32_t bRowLd = wn * 64 + ((lane >> 4) & 1) * 8 + (lane & 7);
    uint32_t bColLd = ((lane >> 3) & 1) * 8;

    cp16(dA0, a0); cp16(dA1, a1); cp16(dB0, b0p); cp16(dB1, b1p);
    CP_COMMIT;

    const int NK = FDIM / 32;   // 88
    for (int ks = 0; ks < NK; ks++) {
        int buf = ks & 1;
        if (ks + 1 < NK) {
            int kk = (ks + 1) * 32;
            uint32_t bo = (buf ^ 1) * BUFB;
            cp16(dA0 + bo, a0 + kk); cp16(dA1 + bo, a1 + kk);
            cp16(dB0 + bo, b0p + kk); cp16(dB1 + bo, b1p + kk);
        }
        CP_COMMIT;
        CP_WAIT1;
        __syncthreads();
        uint32_t bo = buf * BUFB;
        #pragma unroll
        for (int kh = 0; kh < 2; kh++) {
            uint32_t af[2][4];
            #pragma unroll
            for (int i = 0; i < 2; i++) {
                uint32_t ad = sA + bo + ((aRowLd + i * 16) * 40 + aColLd + kh * 16) * 2;
                LDSM4(af[i][0], af[i][1], af[i][2], af[i][3], ad);
            }
            uint32_t bf[8][2];
            #pragma unroll
            for (int jp = 0; jp < 4; jp++) {
                uint32_t bd = sB + bo + ((bRowLd + jp * 16) * 40 + bColLd + kh * 16) * 2;
                LDSM4(bf[jp * 2][0], bf[jp * 2][1], bf[jp * 2 + 1][0], bf[jp * 2 + 1][1], bd);
            }
            #pragma unroll
            for (int i = 0; i < 2; i++)
                #pragma unroll
                for (int j = 0; j < 8; j++)
                    MMA16816(acc[i][j], af[i], bf[j]);
        }
        __syncthreads();
    }

    #pragma unroll
    for (int i = 0; i < 2; i++) {
        int r0 = base + wm * 32 + i * 16 + g;
        int r1 = r0 + 8;
        float w0 = g_wt[r0], w1 = g_wt[r1];
        #pragma unroll
        for (int j = 0; j < 8; j++) {
            int d = ct * 128 + wn * 64 + j * 8 + 2 * tg;
            float2 v0 = make_float2(acc[i][j][0] * w0, acc[i][j][1] * w0);
            float2 v1 = make_float2(acc[i][j][2] * w1, acc[i][j][3] * w1);
            *reinterpret_cast<float2*>(g_og + (size_t)r0 * DDIM + d) = v0;
            *reinterpret_cast<float2*>(g_og + (size_t)r1 * DDIM + d) = v1;
        }
    }
}

// ---------------- combine: out[t] = og[pos0] + og[pos1] ----------------
__global__ void combine_kernel(float* __restrict__ out) {
    int t = blockIdx.x, c = threadIdx.x;  // 256 threads = 1024 floats / 4
    int p0 = g_pos[2 * t], p1 = g_pos[2 * t + 1];
    const float4* r0 = reinterpret_cast<const float4*>(g_og + (size_t)p0 * DDIM);
    const float4* r1 = reinterpret_cast<const float4*>(g_og + (size_t)p1 * DDIM);
    float4 a = r0[c], b = r1[c];
    float4 w = make_float4(a.x + b.x, a.y + b.y, a.z + b.z, a.w + b.w);
    reinterpret_cast<float4*>(out + (size_t)t * DDIM)[c] = w;
}

// ---------------- launch ----------------
extern "C" void kernel_launch(void* const* d_in, const int* in_sizes, int n_in,
                              void* d_out, int out_size) {
    const float* x   = (const float*)d_in[0];
    const float* gup = (const float*)d_in[1];
    const float* dwn = (const float*)d_in[2];
    const float* tw  = (const float*)d_in[3];
    const int*   ti  = (const int*)d_in[4];
    float* out = (float*)d_out;

    prep_kernel<<<1, 256>>>(ti, tw);

    int n4x = T_TOK * DDIM / 4;                 // 1048576
    int n4g = NEXP * TWOF * DDIM / 4;           // 11534336
    int n4d = NEXP * DDIM * FDIM / 4;           // 5767168
    cvt_kernel<<<(n4x + 255) / 256, 256>>>(x,   0, n4x);
    cvt_kernel<<<(n4g + 255) / 256, 256>>>(gup, 1, n4g);
    cvt_kernel<<<(n4d + 255) / 256, 256>>>(dwn, 2, n4d);

    gemm1_kernel<<<dim3(NT1, MAXMT), 256>>>();
    gemm2_kernel<<<dim3(NT2, MAXMT), 256>>>();

    combine_kernel<<<T_TOK, 256>>>(out);
}